// round 13
// baseline (speedup 1.0000x reference)
#include <cuda_runtime.h>
#include <cuda_fp16.h>
#include <cstdint>

#define NNODES 100000
#define NEDGES 625000
#define DIM 128
#define NT 4883           // edge tiles of 128

// ---- k_edge smem: resident W chunks 0,1 + P chunks 2,3 + double-buffered A ----
#define EW_BASE 0         // 32KB
#define EP_BASE 32768     // 32KB
#define EA_BASE 65536     // 2 x 16KB
#define SMEM_EDGE 98304
// ---- k_pre / k_node: per-buffer A(16K)+B(16K), double-buffered ----
#define NBUFSZ 32768
#define SMEM_NODE 65536

// ---- device scratch ----
__device__ int g_src[NEDGES];
__device__ int g_tgt[NEDGES];
__device__ int g_is64;
__device__ int g_degi[NNODES];
__device__ int g_offs[NNODES + 1];
__device__ int g_cursor[NNODES];
__device__ int g_elist[NEDGES];
__device__ uint32_t g_h16[(size_t)NNODES * 64];   // fp16x2-packed h rows
__device__ uint32_t g_agg16[(size_t)NNODES * 64]; // fp16x2 mean-aggregated messages
__device__ uint32_t g_msg16[(size_t)NEDGES * 64]; // fp16x2 per-edge messages
__device__ uint32_t g_Hp[(size_t)NNODES * 64];    // fp16x2 h@P[0:128]
__device__ uint32_t g_Hw1[(size_t)NNODES * 64];   // fp16x2 h@W[128:256]
__device__ uint32_t g_Hw2[(size_t)NNODES * 64];   // fp16x2 h@W[256:384]
__device__ uint32_t g_imgP[4 * 4096];             // swizzled fp16 weight images
__device__ uint32_t g_imgQ[4 * 4096];
__device__ uint32_t g_imgW[6 * 4096];

// ================= helpers =================
__device__ __forceinline__ uint32_t smem_u32(const void* p) {
    uint32_t a;
    asm("{ .reg .u64 t; cvta.to.shared.u64 t, %1; cvt.u32.u64 %0, t; }" : "=r"(a) : "l"(p));
    return a;
}
__device__ __forceinline__ uint32_t cvt_f16x2(float x, float y) {
    uint32_t r;
    asm("cvt.rn.f16x2.f32 %0, %2, %1;" : "=r"(r) : "f"(x), "f"(y));
    return r;
}
__device__ __forceinline__ void ldsm_x4(uint32_t* r, uint32_t addr) {
    asm volatile("ldmatrix.sync.aligned.m8n8.x4.shared.b16 {%0,%1,%2,%3}, [%4];"
                 : "=r"(r[0]), "=r"(r[1]), "=r"(r[2]), "=r"(r[3]) : "r"(addr));
}
__device__ __forceinline__ void mma_f16(float* d, const uint32_t* a, const uint32_t* b) {
    asm volatile(
        "mma.sync.aligned.m16n8k16.row.col.f32.f16.f16.f32 "
        "{%0,%1,%2,%3}, {%4,%5,%6,%7}, {%8,%9}, {%0,%1,%2,%3};"
        : "+f"(d[0]), "+f"(d[1]), "+f"(d[2]), "+f"(d[3])
        : "r"(a[0]), "r"(a[1]), "r"(a[2]), "r"(a[3]), "r"(b[0]), "r"(b[1]));
}
__device__ __forceinline__ void cpa16(uint32_t dst, const void* src) {
    asm volatile("cp.async.cg.shared.global [%0], [%1], 16;" :: "r"(dst), "l"(src));
}
__device__ __forceinline__ void cpa_commit() {
    asm volatile("cp.async.commit_group;" ::: "memory");
}
template <int N>
__device__ __forceinline__ void cpa_wait() {
    asm volatile("cp.async.wait_group %0;" :: "n"(N) : "memory");
}

// ================= prep kernels =================
// zero int degrees + detect index dtype
__global__ void detect_idx(const void* ei) {
    int i = blockIdx.x * blockDim.x + threadIdx.x;
    if (i < NNODES) g_degi[i] = 0;
    if (i == 0) {
        const unsigned long long* p = (const unsigned long long*)ei;
        int is64 = 1;
        for (int k = 0; k < 64; ++k)
            if (p[k] >= (unsigned long long)NNODES) { is64 = 0; break; }
        g_is64 = is64;
    }
}
__global__ void decode_idx(const void* ei) {
    int i = blockIdx.x * blockDim.x + threadIdx.x;
    if (i < NEDGES) {
        long long s, t;
        if (g_is64) { s = ((const long long*)ei)[i]; t = ((const long long*)ei)[NEDGES + i]; }
        else        { s = ((const int*)ei)[i];       t = ((const int*)ei)[NEDGES + i]; }
        if (s < 0) s = 0; if (s >= NNODES) s = NNODES - 1;
        if (t < 0) t = 0; if (t >= NNODES) t = NNODES - 1;
        g_src[i] = (int)s; g_tgt[i] = (int)t;
        atomicAdd(&g_degi[(int)t], 1);
    }
}
// single-CTA exclusive scan of degrees -> offsets + cursors
__global__ void k_scan() {
    __shared__ int tsum[1024];
    const int t = threadIdx.x;
    const int base = t * 98;          // 1024 * 98 = 100352 >= NNODES
    int s = 0;
    for (int i = 0; i < 98; ++i) {
        int n = base + i;
        if (n < NNODES) s += g_degi[n];
    }
    tsum[t] = s;
    __syncthreads();
    if (t == 0) {
        int run = 0;
        for (int i = 0; i < 1024; ++i) { int v = tsum[i]; tsum[i] = run; run += v; }
        g_offs[NNODES] = run;
    }
    __syncthreads();
    int run = tsum[t];
    for (int i = 0; i < 98; ++i) {
        int n = base + i;
        if (n < NNODES) { g_offs[n] = run; g_cursor[n] = run; run += g_degi[n]; }
    }
}
__global__ void k_scatter() {
    int i = blockIdx.x * blockDim.x + threadIdx.x;
    if (i < NEDGES) {
        int pos = atomicAdd(&g_cursor[g_tgt[i]], 1);
        g_elist[pos] = i;
    }
}
__global__ void prep_h(const float* __restrict__ h) {
    size_t id = (size_t)blockIdx.x * blockDim.x + threadIdx.x;
    if (id >= (size_t)NNODES * 32) return;
    float4 v = ((const float4*)h)[id];
    ((uint2*)g_h16)[id] = make_uint2(cvt_f16x2(v.x, v.y), cvt_f16x2(v.z, v.w));
}
__global__ void prep_w_all(const float* __restrict__ Pw, const float* __restrict__ Qw,
                           const float* __restrict__ Ww) {
    int id = blockIdx.x * blockDim.x + threadIdx.x;
    if (id >= 14 * 4096) return;
    int chunk = id >> 12, pos = id & 4095;
    const float* src;
    uint32_t* dst;
    int c;
    if (chunk < 4)      { src = Pw; dst = g_imgP; c = chunk; }
    else if (chunk < 8) { src = Qw; dst = g_imgQ; c = chunk - 4; }
    else                { src = Ww; dst = g_imgW; c = chunk - 8; }
    int n = pos >> 5, kp = pos & 31;
    uint32_t off = n * 128 + kp * 4;
    uint32_t swz = off ^ ((off >> 3) & 0x70);
    int k0 = c * 64 + kp * 2;
    float x = src[(size_t)k0 * DIM + n];
    float y = src[(size_t)(k0 + 1) * DIM + n];
    dst[(c << 12) + (swz >> 2)] = cvt_f16x2(x, y);
}

// ================= fills =================
__device__ __forceinline__ void fill_a_async(uint32_t abase, int row, int half,
                                             const uint32_t* src) {
    const uint32_t mask = (uint32_t)((row & 7) << 4);
    const uint32_t rowbase = abase + (uint32_t)(row * 128);
#pragma unroll
    for (int i = 0; i < 4; ++i) {
        uint32_t off = (((uint32_t)((half * 4 + i) * 16)) ^ mask);
        cpa16(rowbase + off, src + i * 4);
    }
}
__device__ __forceinline__ void lda8(const float* src, int half, float4* pre) {
    const float4* s = (const float4*)src + half * 8;
#pragma unroll
    for (int i = 0; i < 8; ++i) pre[i] = s[i];
}
__device__ __forceinline__ void sta8(char* smem, uint32_t bufofs, int row, int half,
                                     const float4* pre) {
    const uint32_t mask = (uint32_t)((row & 7) << 4);
#pragma unroll
    for (int i = 0; i < 4; ++i) {
        uint4 w;
        w.x = cvt_f16x2(pre[2 * i].x, pre[2 * i].y);
        w.y = cvt_f16x2(pre[2 * i].z, pre[2 * i].w);
        w.z = cvt_f16x2(pre[2 * i + 1].x, pre[2 * i + 1].y);
        w.w = cvt_f16x2(pre[2 * i + 1].z, pre[2 * i + 1].w);
        uint32_t off = (uint32_t)(row * 128) + (((uint32_t)((half * 4 + i) * 16)) ^ mask);
        *(uint4*)(smem + bufofs + off) = w;
    }
}
__device__ __forceinline__ void fill_b_async(uint32_t bbase, const uint32_t* img, int ch,
                                             int tid) {
    const uint32_t* s = img + ((size_t)ch << 12) + tid * 4;
#pragma unroll
    for (int i = 0; i < 4; ++i)
        cpa16(bbase + (uint32_t)((i * 256 + tid) * 16), s + i * 1024);
}

// ================= compute =================
struct Frag {
    uint32_t aOff, aMask, aC0;
    uint32_t bRel, bMask, bC0;
};
__device__ __forceinline__ Frag make_frag(int warp, int lane) {
    Frag f;
    const int mh = warp >> 2, ws = warp & 3;
    f.aOff = (uint32_t)((mh * 64 + (lane & 15)) * 128);
    f.aMask = (uint32_t)((lane & 7) << 4);
    f.aC0 = (uint32_t)(lane >> 4);
    f.bRel = (uint32_t)(ws * 4096 + (lane & 7) * 128 + ((lane >> 4) & 1) * 1024);
    f.bMask = (uint32_t)((lane & 7) << 4);
    f.bC0 = (uint32_t)((lane >> 3) & 1);
    return f;
}
__device__ __forceinline__ void compute_chunk_dual(uint32_t aBase, uint32_t bwBase,
                                                   uint32_t bpBase, const Frag& f,
                                                   float (*dW)[4][4], float (*dP)[4][4]) {
#pragma unroll
    for (int ks = 0; ks < 4; ++ks) {
        const uint32_t aoff = (((f.aC0 + 2 * ks) * 16) ^ f.aMask);
        uint32_t a[4][4];
#pragma unroll
        for (int mf = 0; mf < 4; ++mf)
            ldsm_x4(a[mf], aBase + f.aOff + mf * 2048 + aoff);
        const uint32_t boff = f.bRel + (((f.bC0 + 2 * ks) * 16) ^ f.bMask);
#pragma unroll
        for (int p = 0; p < 2; ++p) {
            uint32_t b[4];
            ldsm_x4(b, bwBase + p * 2048 + boff);
#pragma unroll
            for (int sub = 0; sub < 2; ++sub)
#pragma unroll
                for (int mf = 0; mf < 4; ++mf)
                    mma_f16(dW[mf][p * 2 + sub], a[mf], b + 2 * sub);
            uint32_t bp[4];
            ldsm_x4(bp, bpBase + p * 2048 + boff);
#pragma unroll
            for (int sub = 0; sub < 2; ++sub)
#pragma unroll
                for (int mf = 0; mf < 4; ++mf)
                    mma_f16(dP[mf][p * 2 + sub], a[mf], bp + 2 * sub);
        }
    }
}
__device__ __forceinline__ void compute_chunk(uint32_t aBase, uint32_t bBase, const Frag& f,
                                              float (*d)[4][4]) {
#pragma unroll
    for (int ks = 0; ks < 4; ++ks) {
        const uint32_t aoff = (((f.aC0 + 2 * ks) * 16) ^ f.aMask);
        uint32_t a[4][4];
#pragma unroll
        for (int mf = 0; mf < 4; ++mf)
            ldsm_x4(a[mf], aBase + f.aOff + mf * 2048 + aoff);
        const uint32_t boff = f.bRel + (((f.bC0 + 2 * ks) * 16) ^ f.bMask);
#pragma unroll
        for (int p = 0; p < 2; ++p) {
            uint32_t b[4];
            ldsm_x4(b, bBase + p * 2048 + boff);
#pragma unroll
            for (int sub = 0; sub < 2; ++sub)
#pragma unroll
                for (int mf = 0; mf < 4; ++mf)
                    mma_f16(d[mf][p * 2 + sub], a[mf], b + 2 * sub);
        }
    }
}

// ================= k_pre: node projections Hp / Hw1 / Hw2 (fp16 out) ==========
__global__ __launch_bounds__(256) void k_pre() {
    extern __shared__ char smem[];
    const uint32_t sb = smem_u32(smem);
    const int tid = threadIdx.x, lane = tid & 31, warp = tid >> 5;
    const int n0 = blockIdx.x * 128;
    const int sel = blockIdx.y;
    const uint32_t* img = (sel == 0) ? g_imgP : g_imgW;
    const int cbase = (sel == 0) ? 0 : ((sel == 1) ? 2 : 4);
    uint32_t* out = (sel == 0) ? g_Hp : ((sel == 1) ? g_Hw1 : g_Hw2);
    const int frow = tid >> 1, fhalf = tid & 1;
    const int fng = n0 + frow;
    const int fnode = (fng < NNODES) ? fng : (NNODES - 1);
    const Frag f = make_frag(warp, lane);

    float d[4][4][4];
#pragma unroll
    for (int i = 0; i < 4; ++i)
#pragma unroll
        for (int j = 0; j < 4; ++j)
#pragma unroll
            for (int k = 0; k < 4; ++k) d[i][j][k] = 0.f;

    const uint32_t* as0 = g_h16 + (size_t)fnode * 64 + fhalf * 16;
    const uint32_t* as1 = g_h16 + (size_t)fnode * 64 + 32 + fhalf * 16;

    fill_a_async(sb, frow, fhalf, as0);
    fill_b_async(sb + 16384, img, cbase, tid);
    cpa_commit();
    fill_a_async(sb + NBUFSZ, frow, fhalf, as1);
    fill_b_async(sb + NBUFSZ + 16384, img, cbase + 1, tid);
    cpa_commit();
    cpa_wait<1>();
    __syncthreads();
    compute_chunk(sb, sb + 16384, f, d);
    cpa_wait<0>();
    __syncthreads();
    compute_chunk(sb + NBUFSZ, sb + NBUFSZ + 16384, f, d);

    const int mh = warp >> 2, ws = warp & 3;
    const int r4 = lane >> 2, li = lane & 3;
#pragma unroll
    for (int mf = 0; mf < 4; ++mf) {
#pragma unroll
        for (int half = 0; half < 2; ++half) {
            const int ng = n0 + mh * 64 + mf * 16 + r4 + half * 8;
            if (ng < NNODES) {
                uint32_t* orow = out + (size_t)ng * 64 + ws * 16 + li;
#pragma unroll
                for (int nfl = 0; nfl < 4; ++nfl)
                    orow[nfl * 4] = cvt_f16x2(d[mf][nfl][half * 2 + 0],
                                              d[mf][nfl][half * 2 + 1]);
            }
        }
    }
}

// ================= persistent fused edge kernel =================
// dP = e @ P[128:256];  msg = relu(dP + Hp[src] + pb)  -> fp16 store to g_msg16
// dW = e @ W[0:128];    e_new = relu(dW + Hw1[src] + Hw2[tgt] + wb) -> stg.128
__global__ __launch_bounds__(256, 1) void k_edge(const float* __restrict__ Pb,
                                                 const float* __restrict__ Wb,
                                                 const float* __restrict__ e,
                                                 float* __restrict__ oute) {
    extern __shared__ char smem[];
    const uint32_t sb = smem_u32(smem);
    const int tid = threadIdx.x, lane = tid & 31, warp = tid >> 5;
    const int frow = tid >> 1, fhalf = tid & 1;
    const Frag f = make_frag(warp, lane);
    const int mh = warp >> 2, ws = warp & 3;
    const int r4 = lane >> 2, c2 = (lane & 3) * 2, li = lane & 3;
    const bool evenlane = ((lane & 1) == 0);

    for (int l = tid; l < 2048; l += 256)
        cpa16(sb + EW_BASE + (uint32_t)l * 16, (const char*)g_imgW + (size_t)l * 16);
    for (int l = tid; l < 2048; l += 256)
        cpa16(sb + EP_BASE + (uint32_t)l * 16,
              (const char*)(g_imgP + 2 * 4096) + (size_t)l * 16);
    cpa_commit();
    cpa_wait<0>();
    __syncthreads();

    float2 bPr[4], bWr[4];
#pragma unroll
    for (int nfl = 0; nfl < 4; ++nfl) {
        const int col = ws * 32 + nfl * 8 + c2;
        bPr[nfl] = __ldg((const float2*)(Pb + col));
        bWr[nfl] = __ldg((const float2*)(Wb + col));
    }

    int t = blockIdx.x;
    int fegc;
    const float* e_row;
    {
        int feg = t * 128 + frow;
        fegc = (feg < NEDGES) ? feg : (NEDGES - 1);
        e_row = e + (size_t)fegc * DIM;
        float4 pre[8];
        lda8(e_row, fhalf, pre);
        sta8(smem, EA_BASE, frow, fhalf, pre);
    }

    for (; t < NT; t += (int)gridDim.x) {
        const int e0 = t * 128;
        float dP[4][4][4], dW[4][4][4];
#pragma unroll
        for (int i = 0; i < 4; ++i)
#pragma unroll
            for (int j = 0; j < 4; ++j)
#pragma unroll
                for (int k = 0; k < 4; ++k) { dP[i][j][k] = 0.f; dW[i][j][k] = 0.f; }

        float4 pre[8];
        lda8(e_row + 64, fhalf, pre);
        __syncthreads();
        compute_chunk_dual(sb + EA_BASE, sb + EW_BASE, sb + EP_BASE, f, dW, dP);
        sta8(smem, EA_BASE + 16384, frow, fhalf, pre);
        __syncthreads();
        compute_chunk_dual(sb + EA_BASE + 16384, sb + EW_BASE + 16384,
                           sb + EP_BASE + 16384, f, dW, dP);

        const int tn = t + (int)gridDim.x;
        int fegc_n = 0;
        const float* e_row_n = nullptr;
        if (tn < NT) {
            int feg = tn * 128 + frow;
            fegc_n = (feg < NEDGES) ? feg : (NEDGES - 1);
            e_row_n = e + (size_t)fegc_n * DIM;
            lda8(e_row_n, fhalf, pre);
        }

        // epilogue: gather node projections, bias+relu, store msg (fp16) + e_new
#pragma unroll
        for (int mf = 0; mf < 4; ++mf) {
#pragma unroll
            for (int half = 0; half < 2; ++half) {
                const int eg = e0 + mh * 64 + mf * 16 + r4 + half * 8;
                const bool valid = eg < NEDGES;
                const int egc = valid ? eg : (NEDGES - 1);
                const int s = __ldg(&g_src[egc]);
                const int tv = __ldg(&g_tgt[egc]);
                const uint32_t* hpR = g_Hp + (size_t)s * 64 + ws * 16 + li;
                const uint32_t* h1R = g_Hw1 + (size_t)s * 64 + ws * 16 + li;
                const uint32_t* h2R = g_Hw2 + (size_t)tv * 64 + ws * 16 + li;
                uint32_t* mrow = g_msg16 + (size_t)egc * 64 + ws * 16 + li;
                float* orow = oute + (size_t)egc * DIM;
#pragma unroll
                for (int nfl = 0; nfl < 4; ++nfl) {
                    uint32_t whp = __ldg(hpR + nfl * 4);
                    uint32_t wh1 = __ldg(h1R + nfl * 4);
                    uint32_t wh2 = __ldg(h2R + nfl * 4);
                    float2 hp = __half22float2(*reinterpret_cast<const __half2*>(&whp));
                    float2 h1 = __half22float2(*reinterpret_cast<const __half2*>(&wh1));
                    float2 h2 = __half22float2(*reinterpret_cast<const __half2*>(&wh2));
                    const int col = ws * 32 + nfl * 8 + c2;
                    float2 vP, vW;
                    vP.x = fmaxf(dP[mf][nfl][half * 2 + 0] + hp.x + bPr[nfl].x, 0.f);
                    vP.y = fmaxf(dP[mf][nfl][half * 2 + 1] + hp.y + bPr[nfl].y, 0.f);
                    vW.x = fmaxf(dW[mf][nfl][half * 2 + 0] + h1.x + h2.x + bWr[nfl].x, 0.f);
                    vW.y = fmaxf(dW[mf][nfl][half * 2 + 1] + h1.y + h2.y + bWr[nfl].y, 0.f);
                    float pPx = __shfl_xor_sync(0xffffffffu, vP.x, 1);
                    float pPy = __shfl_xor_sync(0xffffffffu, vP.y, 1);
                    float pWx = __shfl_xor_sync(0xffffffffu, vW.x, 1);
                    float pWy = __shfl_xor_sync(0xffffffffu, vW.y, 1);
                    if (valid && evenlane) {
                        uint2 m;
                        m.x = cvt_f16x2(vP.x, vP.y);
                        m.y = cvt_f16x2(pPx, pPy);
                        *(uint2*)(mrow + nfl * 4) = m;
                        *(float4*)(orow + col) = make_float4(vW.x, vW.y, pWx, pWy);
                    }
                }
            }
        }

        if (tn < NT) sta8(smem, EA_BASE, frow, fhalf, pre);
        fegc = fegc_n;
        e_row = e_row_n;
    }
}

// ================= k_agg: warp-per-node CSR gather-mean (fp16 out) ============
__global__ __launch_bounds__(256) void k_agg() {
    const int w = (int)((blockIdx.x * blockDim.x + threadIdx.x) >> 5);
    const int lane = threadIdx.x & 31;
    if (w >= NNODES) return;
    const int beg = g_offs[w], end = g_offs[w + 1];
    float a0 = 0.f, a1 = 0.f, a2 = 0.f, a3 = 0.f;
    for (int j = beg; j < end; ++j) {
        int eid = __ldg(&g_elist[j]);
        uint2 v = __ldg((const uint2*)(g_msg16 + (size_t)eid * 64 + lane * 2));
        float2 x = __half22float2(*reinterpret_cast<const __half2*>(&v.x));
        float2 y = __half22float2(*reinterpret_cast<const __half2*>(&v.y));
        a0 += x.x; a1 += x.y; a2 += y.x; a3 += y.y;
    }
    const float invd = (end > beg) ? 1.f / (float)(end - beg) : 0.f;
    uint2 o;
    o.x = cvt_f16x2(a0 * invd, a1 * invd);
    o.y = cvt_f16x2(a2 * invd, a3 * invd);
    *(uint2*)(g_agg16 + (size_t)w * 64 + lane * 2) = o;
}

// ================= node kernel (all fills via cp.async) =================
__global__ __launch_bounds__(256) void k_node(const float* __restrict__ Qb,
                                              float* __restrict__ outh) {
    extern __shared__ char smem[];
    const uint32_t sb = smem_u32(smem);
    const int tid = threadIdx.x, lane = tid & 31, warp = tid >> 5;
    const int n0 = blockIdx.x * 128;
    const int frow = tid >> 1, fhalf = tid & 1;
    const int fng = n0 + frow;
    const int fnode = (fng < NNODES) ? fng : (NNODES - 1);
    const Frag f = make_frag(warp, lane);

    float d[4][4][4];
#pragma unroll
    for (int i = 0; i < 4; ++i)
#pragma unroll
        for (int j = 0; j < 4; ++j)
#pragma unroll
            for (int k = 0; k < 4; ++k) d[i][j][k] = 0.f;

    const uint32_t* as[4] = {g_h16 + (size_t)fnode * 64 + fhalf * 16,
                             g_h16 + (size_t)fnode * 64 + 32 + fhalf * 16,
                             g_agg16 + (size_t)fnode * 64 + fhalf * 16,
                             g_agg16 + (size_t)fnode * 64 + 32 + fhalf * 16};

    fill_a_async(sb, frow, fhalf, as[0]);
    fill_b_async(sb + 16384, g_imgQ, 0, tid);
    cpa_commit();
#pragma unroll 1
    for (int ch = 0; ch < 4; ++ch) {
        const uint32_t abase = sb + (uint32_t)((ch & 1) * NBUFSZ);
        if (ch + 1 < 4) {
            const uint32_t nabase = sb + (uint32_t)(((ch + 1) & 1) * NBUFSZ);
            fill_a_async(nabase, frow, fhalf, as[ch + 1]);
            fill_b_async(nabase + 16384, g_imgQ, ch + 1, tid);
            cpa_commit();
            cpa_wait<1>();
        } else {
            cpa_wait<0>();
        }
        __syncthreads();
        compute_chunk(abase, abase + 16384, f, d);
        __syncthreads();
    }

    const int mh = warp >> 2, ws = warp & 3;
    const int r4 = lane >> 2, c2 = (lane & 3) * 2;
    const bool evenlane = ((lane & 1) == 0);
#pragma unroll
    for (int mf = 0; mf < 4; ++mf) {
#pragma unroll
        for (int half = 0; half < 2; ++half) {
            const int ng = n0 + mh * 64 + mf * 16 + r4 + half * 8;
            const bool valid = ng < NNODES;
            float* orow = outh + (size_t)(valid ? ng : 0) * DIM;
#pragma unroll
            for (int nfl = 0; nfl < 4; ++nfl) {
                const int col = ws * 32 + nfl * 8 + c2;
                float2 bias = __ldg((const float2*)(Qb + col));
                float2 v;
                v.x = fmaxf(d[mf][nfl][half * 2 + 0] + bias.x, 0.f);
                v.y = fmaxf(d[mf][nfl][half * 2 + 1] + bias.y, 0.f);
                float px = __shfl_xor_sync(0xffffffffu, v.x, 1);
                float py = __shfl_xor_sync(0xffffffffu, v.y, 1);
                if (valid && evenlane)
                    *(float4*)(orow + col) = make_float4(v.x, v.y, px, py);
            }
        }
    }
}

extern "C" void kernel_launch(void* const* d_in, const int* in_sizes, int n_in,
                              void* d_out, int out_size) {
    const float* h    = (const float*)d_in[0];
    const float* e    = (const float*)d_in[1];
    const void*  eidx = d_in[2];
    const float* Pw   = (const float*)d_in[3];
    const float* Pb   = (const float*)d_in[4];
    const float* Qw   = (const float*)d_in[5];
    const float* Qb   = (const float*)d_in[6];
    const float* Ww   = (const float*)d_in[7];
    const float* Wb   = (const float*)d_in[8];

    float* outh = (float*)d_out;
    float* oute = outh + (size_t)NNODES * DIM;

    cudaFuncSetAttribute(k_pre, cudaFuncAttributeMaxDynamicSharedMemorySize, SMEM_NODE);
    cudaFuncSetAttribute(k_edge, cudaFuncAttributeMaxDynamicSharedMemorySize, SMEM_EDGE);
    cudaFuncSetAttribute(k_node, cudaFuncAttributeMaxDynamicSharedMemorySize, SMEM_NODE);

    const int dblocks = (NEDGES + 255) / 256;
    const int nblocks = (NNODES + 255) / 256;
    const int ng = (NNODES + 127) / 128;   // 782

    detect_idx<<<nblocks, 256>>>(eidx);
    decode_idx<<<dblocks, 256>>>(eidx);
    k_scan<<<1, 1024>>>();
    k_scatter<<<dblocks, 256>>>();
    prep_h<<<(NNODES * 32 + 255) / 256, 256>>>(h);
    prep_w_all<<<224, 256>>>(Pw, Qw, Ww);
    k_pre<<<dim3(ng, 3), 256, SMEM_NODE>>>();
    k_edge<<<148, 256, SMEM_EDGE>>>(Pb, Wb, e, oute);
    k_agg<<<(NNODES * 32 + 255) / 256, 256>>>();
    k_node<<<ng, 256, SMEM_NODE>>>(Qb, outh);
}

// round 14
// speedup vs baseline: 1.4060x; 1.4060x over previous
#include <cuda_runtime.h>
#include <cuda_fp16.h>
#include <cstdint>

#define NNODES 100000
#define NEDGES 625000
#define DIM 128
#define NT2 9766          // edge tiles of 64

// ---- k_edge smem (per CTA, 2 CTAs/SM): resident W0,1 + P2,3 + 2x8KB A ----
#define EW_BASE 0         // 32KB
#define EP_BASE 32768     // 32KB
#define EA_BASE 65536     // 2 x 8KB
#define SMEM_EDGE 81920
// ---- k_pre / k_node: per-buffer A(16K)+B(16K), double-buffered ----
#define NBUFSZ 32768
#define SMEM_NODE 65536

// ---- device scratch ----
__device__ float g_agg[(size_t)NNODES * DIM];
__device__ float g_deg[NNODES];
__device__ int g_src[NEDGES];
__device__ int g_tgt[NEDGES];
__device__ int g_is64;
__device__ uint32_t g_h16[(size_t)NNODES * 64];   // fp16x2-packed h rows
__device__ uint32_t g_Hp[(size_t)NNODES * 64];    // fp16x2 h@P[0:128]
__device__ uint32_t g_Hw1[(size_t)NNODES * 64];   // fp16x2 h@W[128:256]
__device__ uint32_t g_Hw2[(size_t)NNODES * 64];   // fp16x2 h@W[256:384]
__device__ uint32_t g_imgP[4 * 4096];             // swizzled fp16 weight images
__device__ uint32_t g_imgQ[4 * 4096];
__device__ uint32_t g_imgW[6 * 4096];

// ================= helpers =================
__device__ __forceinline__ uint32_t smem_u32(const void* p) {
    uint32_t a;
    asm("{ .reg .u64 t; cvta.to.shared.u64 t, %1; cvt.u32.u64 %0, t; }" : "=r"(a) : "l"(p));
    return a;
}
__device__ __forceinline__ uint32_t cvt_f16x2(float x, float y) {
    uint32_t r;
    asm("cvt.rn.f16x2.f32 %0, %2, %1;" : "=r"(r) : "f"(x), "f"(y));
    return r;
}
__device__ __forceinline__ void ldsm_x4(uint32_t* r, uint32_t addr) {
    asm volatile("ldmatrix.sync.aligned.m8n8.x4.shared.b16 {%0,%1,%2,%3}, [%4];"
                 : "=r"(r[0]), "=r"(r[1]), "=r"(r[2]), "=r"(r[3]) : "r"(addr));
}
__device__ __forceinline__ void mma_f16(float* d, const uint32_t* a, const uint32_t* b) {
    asm volatile(
        "mma.sync.aligned.m16n8k16.row.col.f32.f16.f16.f32 "
        "{%0,%1,%2,%3}, {%4,%5,%6,%7}, {%8,%9}, {%0,%1,%2,%3};"
        : "+f"(d[0]), "+f"(d[1]), "+f"(d[2]), "+f"(d[3])
        : "r"(a[0]), "r"(a[1]), "r"(a[2]), "r"(a[3]), "r"(b[0]), "r"(b[1]));
}
__device__ __forceinline__ void cpa16(uint32_t dst, const void* src) {
    asm volatile("cp.async.cg.shared.global [%0], [%1], 16;" :: "r"(dst), "l"(src));
}
__device__ __forceinline__ void cpa_commit() {
    asm volatile("cp.async.commit_group;" ::: "memory");
}
template <int N>
__device__ __forceinline__ void cpa_wait() {
    asm volatile("cp.async.wait_group %0;" :: "n"(N) : "memory");
}
__device__ __forceinline__ void red_v4(float* ptr, float a, float b, float c, float d) {
    asm volatile("red.global.v4.f32.add [%0], {%1, %2, %3, %4};"
                 :: "l"(ptr), "f"(a), "f"(b), "f"(c), "f"(d) : "memory");
}

// ================= prep kernels =================
__global__ void detect_idx(const void* ei) {
    if (threadIdx.x == 0 && blockIdx.x == 0) {
        const unsigned long long* p = (const unsigned long long*)ei;
        int is64 = 1;
        for (int i = 0; i < 64; ++i)
            if (p[i] >= (unsigned long long)NNODES) { is64 = 0; break; }
        g_is64 = is64;
    }
}
__global__ void decode_idx(const void* ei) {
    int i = blockIdx.x * blockDim.x + threadIdx.x;
    size_t stride = (size_t)gridDim.x * blockDim.x;
    for (size_t j = i; j < (size_t)NNODES * DIM; j += stride) g_agg[j] = 0.f;
    for (size_t j = i; j < NNODES; j += stride) g_deg[j] = 0.f;
    if (i < NEDGES) {
        long long s, t;
        if (g_is64) { s = ((const long long*)ei)[i]; t = ((const long long*)ei)[NEDGES + i]; }
        else        { s = ((const int*)ei)[i];       t = ((const int*)ei)[NEDGES + i]; }
        if (s < 0) s = 0; if (s >= NNODES) s = NNODES - 1;
        if (t < 0) t = 0; if (t >= NNODES) t = NNODES - 1;
        g_src[i] = (int)s; g_tgt[i] = (int)t;
    }
}
__global__ void count_deg() {
    int i = blockIdx.x * blockDim.x + threadIdx.x;
    if (i < NEDGES) atomicAdd(&g_deg[g_tgt[i]], 1.f);
}
__global__ void prep_h(const float* __restrict__ h) {
    size_t id = (size_t)blockIdx.x * blockDim.x + threadIdx.x;
    if (id >= (size_t)NNODES * 32) return;
    float4 v = ((const float4*)h)[id];
    ((uint2*)g_h16)[id] = make_uint2(cvt_f16x2(v.x, v.y), cvt_f16x2(v.z, v.w));
}
__global__ void prep_w_all(const float* __restrict__ Pw, const float* __restrict__ Qw,
                           const float* __restrict__ Ww) {
    int id = blockIdx.x * blockDim.x + threadIdx.x;
    if (id >= 14 * 4096) return;
    int chunk = id >> 12, pos = id & 4095;
    const float* src;
    uint32_t* dst;
    int c;
    if (chunk < 4)      { src = Pw; dst = g_imgP; c = chunk; }
    else if (chunk < 8) { src = Qw; dst = g_imgQ; c = chunk - 4; }
    else                { src = Ww; dst = g_imgW; c = chunk - 8; }
    int n = pos >> 5, kp = pos & 31;
    uint32_t off = n * 128 + kp * 4;
    uint32_t swz = off ^ ((off >> 3) & 0x70);
    int k0 = c * 64 + kp * 2;
    float x = src[(size_t)k0 * DIM + n];
    float y = src[(size_t)(k0 + 1) * DIM + n];
    dst[(c << 12) + (swz >> 2)] = cvt_f16x2(x, y);
}

// ================= fills (128-row tiles, k_pre/k_node) =================
__device__ __forceinline__ void fill_a_async(uint32_t abase, int row, int half,
                                             const uint32_t* src) {
    const uint32_t mask = (uint32_t)((row & 7) << 4);
    const uint32_t rowbase = abase + (uint32_t)(row * 128);
#pragma unroll
    for (int i = 0; i < 4; ++i) {
        uint32_t off = (((uint32_t)((half * 4 + i) * 16)) ^ mask);
        cpa16(rowbase + off, src + i * 4);
    }
}
__device__ __forceinline__ void fill_a_f32(char* smem, uint32_t bufofs, int row, int half,
                                           const float* src, float sc) {
    const float4* s = (const float4*)src + half * 8;
    const uint32_t mask = (uint32_t)((row & 7) << 4);
#pragma unroll
    for (int i = 0; i < 4; ++i) {
        float4 a = s[2 * i], b = s[2 * i + 1];
        uint4 w;
        w.x = cvt_f16x2(a.x * sc, a.y * sc);
        w.y = cvt_f16x2(a.z * sc, a.w * sc);
        w.z = cvt_f16x2(b.x * sc, b.y * sc);
        w.w = cvt_f16x2(b.z * sc, b.w * sc);
        uint32_t off = (uint32_t)(row * 128) + (((uint32_t)((half * 4 + i) * 16)) ^ mask);
        *(uint4*)(smem + bufofs + off) = w;
    }
}
__device__ __forceinline__ void fill_b_async(uint32_t bbase, const uint32_t* img, int ch,
                                             int tid) {
    const uint32_t* s = img + ((size_t)ch << 12) + tid * 4;
#pragma unroll
    for (int i = 0; i < 4; ++i)
        cpa16(bbase + (uint32_t)((i * 256 + tid) * 16), s + i * 1024);
}
// ---- 64-row tile fills (k_edge): 4 threads/row, 2x16B each ----
__device__ __forceinline__ void lda4(const float* src, int fq, float4* pre) {
    const float4* s = (const float4*)src + fq * 4;
#pragma unroll
    for (int i = 0; i < 4; ++i) pre[i] = s[i];
}
__device__ __forceinline__ void sta4(char* smem, uint32_t bufofs, int row, int fq,
                                     const float4* pre) {
    const uint32_t mask = (uint32_t)((row & 7) << 4);
#pragma unroll
    for (int i = 0; i < 2; ++i) {
        uint4 w;
        w.x = cvt_f16x2(pre[2 * i].x, pre[2 * i].y);
        w.y = cvt_f16x2(pre[2 * i].z, pre[2 * i].w);
        w.z = cvt_f16x2(pre[2 * i + 1].x, pre[2 * i + 1].y);
        w.w = cvt_f16x2(pre[2 * i + 1].z, pre[2 * i + 1].w);
        uint32_t off = (uint32_t)(row * 128) + (((uint32_t)((2 * fq + i) * 16)) ^ mask);
        *(uint4*)(smem + bufofs + off) = w;
    }
}

// ================= compute =================
struct Frag {
    uint32_t aOff, aMask, aC0;
    uint32_t bRel, bMask, bC0;
};
// 128-row tiles (k_pre / k_node)
__device__ __forceinline__ Frag make_frag(int warp, int lane) {
    Frag f;
    const int mh = warp >> 2, ws = warp & 3;
    f.aOff = (uint32_t)((mh * 64 + (lane & 15)) * 128);
    f.aMask = (uint32_t)((lane & 7) << 4);
    f.aC0 = (uint32_t)(lane >> 4);
    f.bRel = (uint32_t)(ws * 4096 + (lane & 7) * 128 + ((lane >> 4) & 1) * 1024);
    f.bMask = (uint32_t)((lane & 7) << 4);
    f.bC0 = (uint32_t)((lane >> 3) & 1);
    return f;
}
// 64-row tiles (k_edge): warp covers rows [mh*32, mh*32+32)
__device__ __forceinline__ Frag make_frag64(int warp, int lane) {
    Frag f;
    const int mh = warp >> 2, ws = warp & 3;
    f.aOff = (uint32_t)((mh * 32 + (lane & 15)) * 128);
    f.aMask = (uint32_t)((lane & 7) << 4);
    f.aC0 = (uint32_t)(lane >> 4);
    f.bRel = (uint32_t)(ws * 4096 + (lane & 7) * 128 + ((lane >> 4) & 1) * 1024);
    f.bMask = (uint32_t)((lane & 7) << 4);
    f.bC0 = (uint32_t)((lane >> 3) & 1);
    return f;
}
__device__ __forceinline__ void compute_chunk(uint32_t aBase, uint32_t bBase, const Frag& f,
                                              float (*d)[4][4]) {
#pragma unroll
    for (int ks = 0; ks < 4; ++ks) {
        const uint32_t aoff = (((f.aC0 + 2 * ks) * 16) ^ f.aMask);
        uint32_t a[4][4];
#pragma unroll
        for (int mf = 0; mf < 4; ++mf)
            ldsm_x4(a[mf], aBase + f.aOff + mf * 2048 + aoff);
        const uint32_t boff = f.bRel + (((f.bC0 + 2 * ks) * 16) ^ f.bMask);
#pragma unroll
        for (int p = 0; p < 2; ++p) {
            uint32_t b[4];
            ldsm_x4(b, bBase + p * 2048 + boff);
#pragma unroll
            for (int sub = 0; sub < 2; ++sub)
#pragma unroll
                for (int mf = 0; mf < 4; ++mf)
                    mma_f16(d[mf][p * 2 + sub], a[mf], b + 2 * sub);
        }
    }
}
// M=64 dual (k_edge): 2 m-frags, both B operands
__device__ __forceinline__ void compute_chunk_dual64(uint32_t aBase, uint32_t bwBase,
                                                     uint32_t bpBase, const Frag& f,
                                                     float (*dW)[4][4], float (*dP)[4][4]) {
#pragma unroll
    for (int ks = 0; ks < 4; ++ks) {
        const uint32_t aoff = (((f.aC0 + 2 * ks) * 16) ^ f.aMask);
        uint32_t a[2][4];
#pragma unroll
        for (int mf = 0; mf < 2; ++mf)
            ldsm_x4(a[mf], aBase + f.aOff + mf * 2048 + aoff);
        const uint32_t boff = f.bRel + (((f.bC0 + 2 * ks) * 16) ^ f.bMask);
#pragma unroll
        for (int p = 0; p < 2; ++p) {
            uint32_t b[4];
            ldsm_x4(b, bwBase + p * 2048 + boff);
#pragma unroll
            for (int sub = 0; sub < 2; ++sub)
#pragma unroll
                for (int mf = 0; mf < 2; ++mf)
                    mma_f16(dW[mf][p * 2 + sub], a[mf], b + 2 * sub);
            uint32_t bp[4];
            ldsm_x4(bp, bpBase + p * 2048 + boff);
#pragma unroll
            for (int sub = 0; sub < 2; ++sub)
#pragma unroll
                for (int mf = 0; mf < 2; ++mf)
                    mma_f16(dP[mf][p * 2 + sub], a[mf], bp + 2 * sub);
        }
    }
}

// ================= k_pre: node projections Hp / Hw1 / Hw2 (fp16 out) ==========
__global__ __launch_bounds__(256) void k_pre() {
    extern __shared__ char smem[];
    const uint32_t sb = smem_u32(smem);
    const int tid = threadIdx.x, lane = tid & 31, warp = tid >> 5;
    const int n0 = blockIdx.x * 128;
    const int sel = blockIdx.y;
    const uint32_t* img = (sel == 0) ? g_imgP : g_imgW;
    const int cbase = (sel == 0) ? 0 : ((sel == 1) ? 2 : 4);
    uint32_t* out = (sel == 0) ? g_Hp : ((sel == 1) ? g_Hw1 : g_Hw2);
    const int frow = tid >> 1, fhalf = tid & 1;
    const int fng = n0 + frow;
    const int fnode = (fng < NNODES) ? fng : (NNODES - 1);
    const Frag f = make_frag(warp, lane);

    float d[4][4][4];
#pragma unroll
    for (int i = 0; i < 4; ++i)
#pragma unroll
        for (int j = 0; j < 4; ++j)
#pragma unroll
            for (int k = 0; k < 4; ++k) d[i][j][k] = 0.f;

    const uint32_t* as0 = g_h16 + (size_t)fnode * 64 + fhalf * 16;
    const uint32_t* as1 = g_h16 + (size_t)fnode * 64 + 32 + fhalf * 16;

    fill_a_async(sb, frow, fhalf, as0);
    fill_b_async(sb + 16384, img, cbase, tid);
    cpa_commit();
    fill_a_async(sb + NBUFSZ, frow, fhalf, as1);
    fill_b_async(sb + NBUFSZ + 16384, img, cbase + 1, tid);
    cpa_commit();
    cpa_wait<1>();
    __syncthreads();
    compute_chunk(sb, sb + 16384, f, d);
    cpa_wait<0>();
    __syncthreads();
    compute_chunk(sb + NBUFSZ, sb + NBUFSZ + 16384, f, d);

    const int mh = warp >> 2, ws = warp & 3;
    const int r4 = lane >> 2, li = lane & 3;
#pragma unroll
    for (int mf = 0; mf < 4; ++mf) {
#pragma unroll
        for (int half = 0; half < 2; ++half) {
            const int ng = n0 + mh * 64 + mf * 16 + r4 + half * 8;
            if (ng < NNODES) {
                uint32_t* orow = out + (size_t)ng * 64 + ws * 16 + li;
#pragma unroll
                for (int nfl = 0; nfl < 4; ++nfl)
                    orow[nfl * 4] = cvt_f16x2(d[mf][nfl][half * 2 + 0],
                                              d[mf][nfl][half * 2 + 1]);
            }
        }
    }
}

// ================= persistent fused edge kernel (M=64, 2 CTAs/SM) =============
// dP = e @ P[128:256];  msg = relu(dP + Hp[src] + pb)  -> red.v4 into g_agg[tgt]
// dW = e @ W[0:128];    e_new = relu(dW + Hw1[src] + Hw2[tgt] + wb) -> stg.128
__global__ __launch_bounds__(256, 2) void k_edge(const float* __restrict__ Pb,
                                                 const float* __restrict__ Wb,
                                                 const float* __restrict__ e,
                                                 float* __restrict__ oute) {
    extern __shared__ char smem[];
    const uint32_t sb = smem_u32(smem);
    const int tid = threadIdx.x, lane = tid & 31, warp = tid >> 5;
    const int frow = tid >> 2, fq = tid & 3;
    const Frag f = make_frag64(warp, lane);
    const int mh = warp >> 2, ws = warp & 3;
    const int r4 = lane >> 2, c2 = (lane & 3) * 2, li = lane & 3;
    const bool evenlane = ((lane & 1) == 0);

    // resident weights: W chunks 0,1 ; P chunks 2,3
    for (int l = tid; l < 2048; l += 256)
        cpa16(sb + EW_BASE + (uint32_t)l * 16, (const char*)g_imgW + (size_t)l * 16);
    for (int l = tid; l < 2048; l += 256)
        cpa16(sb + EP_BASE + (uint32_t)l * 16,
              (const char*)(g_imgP + 2 * 4096) + (size_t)l * 16);
    cpa_commit();
    cpa_wait<0>();
    __syncthreads();

    // hoisted biases (tile-invariant)
    float2 bPr[4], bWr[4];
#pragma unroll
    for (int nfl = 0; nfl < 4; ++nfl) {
        const int col = ws * 32 + nfl * 8 + c2;
        bPr[nfl] = __ldg((const float2*)(Pb + col));
        bWr[nfl] = __ldg((const float2*)(Wb + col));
    }

    int t = blockIdx.x;
    int fegc;
    const float* e_row;
    {
        int feg = t * 64 + frow;
        fegc = (feg < NEDGES) ? feg : (NEDGES - 1);
        e_row = e + (size_t)fegc * DIM;
        float4 pre[4];
        lda4(e_row, fq, pre);
        sta4(smem, EA_BASE, frow, fq, pre);   // chunk 0 = e[0:64] into A buf0
    }

    for (; t < NT2; t += (int)gridDim.x) {
        const int e0 = t * 64;
        float dP[2][4][4], dW[2][4][4];
#pragma unroll
        for (int i = 0; i < 2; ++i)
#pragma unroll
            for (int j = 0; j < 4; ++j)
#pragma unroll
                for (int k = 0; k < 4; ++k) { dP[i][j][k] = 0.f; dW[i][j][k] = 0.f; }

        float4 pre[4];
        lda4(e_row + 64, fq, pre);           // e[64:128] LDGs in flight
        __syncthreads();                      // buf0 visible
        compute_chunk_dual64(sb + EA_BASE, sb + EW_BASE, sb + EP_BASE, f, dW, dP);
        sta4(smem, EA_BASE + 8192, frow, fq, pre);
        __syncthreads();
        compute_chunk_dual64(sb + EA_BASE + 8192, sb + EW_BASE + 16384,
                             sb + EP_BASE + 16384, f, dW, dP);

        // prefetch next tile's e[0:64]
        const int tn = t + (int)gridDim.x;
        int fegc_n = 0;
        const float* e_row_n = nullptr;
        if (tn < NT2) {
            int feg = tn * 64 + frow;
            fegc_n = (feg < NEDGES) ? feg : (NEDGES - 1);
            e_row_n = e + (size_t)fegc_n * DIM;
            lda4(e_row_n, fq, pre);
        }

        // epilogue: gather node projections, bias+relu, scatter/store
#pragma unroll
        for (int mf = 0; mf < 2; ++mf) {
#pragma unroll
            for (int half = 0; half < 2; ++half) {
                const int eg = e0 + mh * 32 + mf * 16 + r4 + half * 8;
                const bool valid = eg < NEDGES;
                const int egc = valid ? eg : (NEDGES - 1);
                const int s = __ldg(&g_src[egc]);
                const int tv = __ldg(&g_tgt[egc]);
                const uint32_t* hpR = g_Hp + (size_t)s * 64 + ws * 16 + li;
                const uint32_t* h1R = g_Hw1 + (size_t)s * 64 + ws * 16 + li;
                const uint32_t* h2R = g_Hw2 + (size_t)tv * 64 + ws * 16 + li;
                float* arow = g_agg + (size_t)tv * DIM;
                float* orow = oute + (size_t)egc * DIM;
#pragma unroll
                for (int nfl = 0; nfl < 4; ++nfl) {
                    uint32_t whp = __ldg(hpR + nfl * 4);
                    uint32_t wh1 = __ldg(h1R + nfl * 4);
                    uint32_t wh2 = __ldg(h2R + nfl * 4);
                    float2 hp = __half22float2(*reinterpret_cast<const __half2*>(&whp));
                    float2 h1 = __half22float2(*reinterpret_cast<const __half2*>(&wh1));
                    float2 h2 = __half22float2(*reinterpret_cast<const __half2*>(&wh2));
                    const int col = ws * 32 + nfl * 8 + c2;
                    float2 vP, vW;
                    vP.x = fmaxf(dP[mf][nfl][half * 2 + 0] + hp.x + bPr[nfl].x, 0.f);
                    vP.y = fmaxf(dP[mf][nfl][half * 2 + 1] + hp.y + bPr[nfl].y, 0.f);
                    vW.x = fmaxf(dW[mf][nfl][half * 2 + 0] + h1.x + h2.x + bWr[nfl].x, 0.f);
                    vW.y = fmaxf(dW[mf][nfl][half * 2 + 1] + h1.y + h2.y + bWr[nfl].y, 0.f);
                    float pPx = __shfl_xor_sync(0xffffffffu, vP.x, 1);
                    float pPy = __shfl_xor_sync(0xffffffffu, vP.y, 1);
                    float pWx = __shfl_xor_sync(0xffffffffu, vW.x, 1);
                    float pWy = __shfl_xor_sync(0xffffffffu, vW.y, 1);
                    if (valid && evenlane) {
                        red_v4(arow + col, vP.x, vP.y, pPx, pPy);
                        *(float4*)(orow + col) = make_float4(vW.x, vW.y, pWx, pWy);
                    }
                }
            }
        }

        if (tn < NT2) sta4(smem, EA_BASE, frow, fq, pre);
        fegc = fegc_n;
        e_row = e_row_n;
    }
}

// ================= node kernel =================
__global__ __launch_bounds__(256) void k_node(const float* __restrict__ Qb,
                                              float* __restrict__ outh) {
    extern __shared__ char smem[];
    const uint32_t sb = smem_u32(smem);
    const int tid = threadIdx.x, lane = tid & 31, warp = tid >> 5;
    const int n0 = blockIdx.x * 128;
    const int frow = tid >> 1, fhalf = tid & 1;
    const int fng = n0 + frow;
    const int fnode = (fng < NNODES) ? fng : (NNODES - 1);
    const float finvd = 1.f / fmaxf(g_deg[fnode], 1.f);
    const Frag f = make_frag(warp, lane);

    float d[4][4][4];
#pragma unroll
    for (int i = 0; i < 4; ++i)
#pragma unroll
        for (int j = 0; j < 4; ++j)
#pragma unroll
            for (int k = 0; k < 4; ++k) d[i][j][k] = 0.f;

    const uint32_t* as[2] = {g_h16 + (size_t)fnode * 64 + fhalf * 16,
                             g_h16 + (size_t)fnode * 64 + 32 + fhalf * 16};

    fill_a_async(sb, frow, fhalf, as[0]);
    fill_b_async(sb + 16384, g_imgQ, 0, tid);
    cpa_commit();
#pragma unroll 1
    for (int ch = 0; ch < 4; ++ch) {
        const uint32_t abase = sb + (uint32_t)((ch & 1) * NBUFSZ);
        if (ch + 1 < 4) {
            const uint32_t nabase = sb + (uint32_t)(((ch + 1) & 1) * NBUFSZ);
            if (ch + 1 < 2) fill_a_async(nabase, frow, fhalf, as[ch + 1]);
            else fill_a_f32(smem, ((ch + 1) & 1) * NBUFSZ, frow, fhalf,
                            g_agg + (size_t)fnode * DIM + (ch + 1 - 2) * 64, finvd);
            fill_b_async(nabase + 16384, g_imgQ, ch + 1, tid);
            cpa_commit();
            cpa_wait<1>();
        } else {
            cpa_wait<0>();
        }
        __syncthreads();
        compute_chunk(abase, abase + 16384, f, d);
        __syncthreads();
    }

    const int mh = warp >> 2, ws = warp & 3;
    const int r4 = lane >> 2, c2 = (lane & 3) * 2;
    const bool evenlane = ((lane & 1) == 0);
#pragma unroll
    for (int mf = 0; mf < 4; ++mf) {
#pragma unroll
        for (int half = 0; half < 2; ++half) {
            const int ng = n0 + mh * 64 + mf * 16 + r4 + half * 8;
            const bool valid = ng < NNODES;
            float* orow = outh + (size_t)(valid ? ng : 0) * DIM;
#pragma unroll
            for (int nfl = 0; nfl < 4; ++nfl) {
                const int col = ws * 32 + nfl * 8 + c2;
                float2 bias = __ldg((const float2*)(Qb + col));
                float2 v;
                v.x = fmaxf(d[mf][nfl][half * 2 + 0] + bias.x, 0.f);
                v.y = fmaxf(d[mf][nfl][half * 2 + 1] + bias.y, 0.f);
                float px = __shfl_xor_sync(0xffffffffu, v.x, 1);
                float py = __shfl_xor_sync(0xffffffffu, v.y, 1);
                if (valid && evenlane)
                    *(float4*)(orow + col) = make_float4(v.x, v.y, px, py);
            }
        }
    }
}

extern "C" void kernel_launch(void* const* d_in, const int* in_sizes, int n_in,
                              void* d_out, int out_size) {
    const float* h    = (const float*)d_in[0];
    const float* e    = (const float*)d_in[1];
    const void*  eidx = d_in[2];
    const float* Pw   = (const float*)d_in[3];
    const float* Pb   = (const float*)d_in[4];
    const float* Qw   = (const float*)d_in[5];
    const float* Qb   = (const float*)d_in[6];
    const float* Ww   = (const float*)d_in[7];
    const float* Wb   = (const float*)d_in[8];

    float* outh = (float*)d_out;
    float* oute = outh + (size_t)NNODES * DIM;

    cudaFuncSetAttribute(k_pre, cudaFuncAttributeMaxDynamicSharedMemorySize, SMEM_NODE);
    cudaFuncSetAttribute(k_edge, cudaFuncAttributeMaxDynamicSharedMemorySize, SMEM_EDGE);
    cudaFuncSetAttribute(k_node, cudaFuncAttributeMaxDynamicSharedMemorySize, SMEM_NODE);

    const int dblocks = (NEDGES + 255) / 256;
    const int ng = (NNODES + 127) / 128;   // 782

    detect_idx<<<1, 32>>>(eidx);
    decode_idx<<<dblocks, 256>>>(eidx);
    count_deg<<<dblocks, 256>>>();
    prep_h<<<(NNODES * 32 + 255) / 256, 256>>>(h);
    prep_w_all<<<224, 256>>>(Pw, Qw, Ww);
    k_pre<<<dim3(ng, 3), 256, SMEM_NODE>>>();
    k_edge<<<296, 256, SMEM_EDGE>>>(Pb, Wb, e, oute);
    k_node<<<ng, 256, SMEM_NODE>>>(Qb, outh);
}